// round 13
// baseline (speedup 1.0000x reference)
#include <cuda_runtime.h>
#include <cuda_bf16.h>
#include <cuda_fp16.h>

#define Bn 128
#define Vn 1024
#define Tn 1024
#define Cn 1024
#define VT 16   // v-columns per CTA in the attention kernel (8 warps x 2 cols)

typedef unsigned long long u64;

// Scratch (allocation-free rule: __device__ globals).
// g_zero = [ g_vs (Bn*Tn) | g_acc (Bn*Cn) ]  -> single memset per launch.
__device__ float g_zero[Bn * Tn + Bn * Cn];
__device__ float g_ts[Bn * Vn];   // text_score, written exactly once

__device__ __forceinline__ float ftanh_approx(float x) {
    float r;
    asm("tanh.approx.f32 %0, %1;" : "=f"(r) : "f"(x));
    return r;
}

// Pack two f32 into one f16x2 register with a single SASS op.
__device__ __forceinline__ unsigned pack_f16x2(float lo, float hi) {
    unsigned p;
    asm("cvt.rn.f16x2.f32 %0, %1, %2;" : "=r"(p) : "f"(hi), "f"(lo));
    return p;
}

// ---- packed fp32x2 (SASS FFMA2) helpers ----
__device__ __forceinline__ u64 f2fma(u64 a, u64 b, u64 c) {
    u64 d;
    asm("fma.rn.f32x2 %0, %1, %2, %3;" : "=l"(d) : "l"(a), "l"(b), "l"(c));
    return d;
}
__device__ __forceinline__ u64 f2add(u64 a, u64 b) {
    u64 d;
    asm("add.rn.f32x2 %0, %1, %2;" : "=l"(d) : "l"(a), "l"(b));
    return d;
}
__device__ __forceinline__ u64 f2pack(float lo, float hi) {
    u64 d;
    asm("mov.b64 %0, {%1, %2};" : "=l"(d) : "f"(lo), "f"(hi));
    return d;
}
__device__ __forceinline__ float2 f2unpack(u64 v) {
    float2 r;
    asm("mov.b64 {%0, %1}, %2;" : "=f"(r.x), "=f"(r.y) : "l"(v));
    return r;
}

// ---------------------------------------------------------------------------
// Kernel 1: fused scores/tanh/softmax/reductions.
// s in f32; u = tanh.approx.f32(s) (ONLY MUFU op, 1/elem);
// E = exp(u) via degree-6 Taylor Horner in PACKED fma.rn.f32x2 (u in (-1,1),
// worst-case rel err 2e-4 at |u|->1, <1e-5 in the operating range).
// f16 slab STORAGE only; Z/N accumulate in packed f32x2 (== two f32 scalars).
// Grid: (Vn/VT, Bn). Block: 256 (8 warps, 2 v-cols per warp).
// SMEM: slab 32KB + wy 8KB + g2 32B -> 5 CTAs/SM.
// ---------------------------------------------------------------------------
extern __shared__ float smem_dyn[];

__global__ __launch_bounds__(256, 5) void attn_pass_kernel(
    const float* __restrict__ vis,     // [B, V]
    const float* __restrict__ txt,     // [B, T]
    const float* __restrict__ w_vis,   // [T]
    const float* __restrict__ w_text,  // [V]
    const float* __restrict__ bias)    // [V]
{
    __half2* e   = (__half2*)smem_dyn;                 // 8 warps x Tn (half2 = col pair)
    float2*  wy  = (float2*)(smem_dyn + 2 * 4096);     // Tn x (w, y)
    __half2* g2s = (__half2*)(wy + Tn);                // 8 packed (g0,g1) pairs

    float* g_vs = g_zero;

    const int b   = blockIdx.y;
    const int v0  = blockIdx.x * VT;
    const int tid = threadIdx.x;

    for (int i = tid; i < Tn; i += 256)
        wy[i] = make_float2(w_vis[i], txt[b * Tn + i]);
    __syncthreads();

    const int warp = tid >> 5;
    const int lane = tid & 31;
    const int vl   = warp * 2;

    float x0, x1, c0, c1, bv0, bv1;
    {
        int vg = v0 + vl;
        x0  = vis[b * Vn + vg];
        x1  = vis[b * Vn + vg + 1];
        c0  = w_text[vg];
        c1  = w_text[vg + 1];
        bv0 = bias[vg];
        bv1 = bias[vg + 1];
    }

    // Taylor coefficients of exp(u), packed (both lanes identical)
    const u64 C6  = f2pack(1.388888889e-3f, 1.388888889e-3f);  // 1/720
    const u64 C5  = f2pack(8.333333333e-3f, 8.333333333e-3f);  // 1/120
    const u64 C4  = f2pack(4.166666667e-2f, 4.166666667e-2f);  // 1/24
    const u64 C3  = f2pack(1.666666667e-1f, 1.666666667e-1f);  // 1/6
    const u64 C2  = f2pack(0.5f, 0.5f);
    const u64 ONE = f2pack(1.0f, 1.0f);

    u64 Zp = 0ull;   // (Z0, Z1) packed f32x2
    u64 Np = 0ull;   // (N0, N1) packed f32x2

    unsigned* erow = (unsigned*)(e + warp * Tn);

    // Main loop over T. s = x*w + y*c + bias; u = tanh(s); E = exp(u) poly.
#pragma unroll 8
    for (int i = 0; i < 32; i++) {
        int t = lane + 32 * i;
        float2 p = wy[t];
        float w = p.x, y = p.y;

        float s0 = fmaf(x0, w, fmaf(y, c0, bv0));
        float s1 = fmaf(x1, w, fmaf(y, c1, bv1));
        float u0 = ftanh_approx(s0);          // the only MUFU ops
        float u1 = ftanh_approx(s1);

        u64 u = f2pack(u0, u1);
        u64 q = f2fma(C6, u, C5);             // Horner, both cols per instr
        q = f2fma(q, u, C4);
        q = f2fma(q, u, C3);
        q = f2fma(q, u, C2);
        q = f2fma(q, u, ONE);                 // + c1 (=1)
        q = f2fma(q, u, ONE);                 // + c0 (=1)  -> E = exp(u)

        float2 Ef = f2unpack(q);
        erow[t] = pack_f16x2(Ef.x, Ef.y);

        Zp = f2add(Zp, q);
        Np = f2fma(q, f2pack(y, y), Np);
    }

    float2 Zf = f2unpack(Zp);
    float2 Nf = f2unpack(Np);
    float Z0 = Zf.x, Z1 = Zf.y, N0 = Nf.x, N1 = Nf.y;

    // Warp reductions for Z and the text numerator
#pragma unroll
    for (int o = 16; o > 0; o >>= 1) {
        Z0 += __shfl_xor_sync(0xffffffffu, Z0, o);
        Z1 += __shfl_xor_sync(0xffffffffu, Z1, o);
        N0 += __shfl_xor_sync(0xffffffffu, N0, o);
        N1 += __shfl_xor_sync(0xffffffffu, N1, o);
    }

    if (lane == 0) {
        float iZ0 = 1.0f / Z0;
        float iZ1 = 1.0f / Z1;
        g_ts[b * Vn + v0 + vl]     = N0 * iZ0;
        g_ts[b * Vn + v0 + vl + 1] = N1 * iZ1;
        g2s[warp] = __floats2half2_rn(x0 * iZ0, x1 * iZ1);
    }
    __syncthreads();

    // Pass 2: visual partial per t, native half2 FMA (no per-element cvt)
    __half2 gr[8];
#pragma unroll
    for (int w8 = 0; w8 < 8; w8++) gr[w8] = g2s[w8];

#pragma unroll
    for (int i = 0; i < 4; i++) {
        int t = tid + 256 * i;
        __half2 acc2 = __float2half2_rn(0.f);
#pragma unroll
        for (int w8 = 0; w8 < 8; w8++)
            acc2 = __hfma2(e[w8 * Tn + t], gr[w8], acc2);
        float acc = __low2float(acc2) + __high2float(acc2);
        atomicAdd(&g_vs[b * Tn + t], acc);
    }
}

// ---------------------------------------------------------------------------
// Kernel 2: split-K GEMM, double-buffered, full-wave grid.  (R10 proven)
// Grid: (16 c-tiles, 16 k-slices) = 256 CTAs. K=128/CTA, KC=32, 4 iters.
// Microtile: 4 b-row-pairs (FFMA2) x 4 cols.
// ---------------------------------------------------------------------------
#define KC 32

__global__ __launch_bounds__(256, 1) void gemm_split_kernel(
    const float* __restrict__ Wfv,  // [C, T]
    const float* __restrict__ Wft)  // [C, V]
{
    __shared__ float As[2][KC][128];
    __shared__ float Ws[2][KC][64];

    float* g_vs  = g_zero;
    float* g_acc = g_zero + Bn * Tn;

    const int ctile = blockIdx.x;
    const int ks    = blockIdx.y;

    const float* A;
    const float* W;
    int k0;
    if (ks < 8) { A = g_vs; W = Wfv; k0 = ks * 128; }
    else        { A = g_ts; W = Wft; k0 = (ks - 8) * 128; }

    const int c0  = ctile * 64;
    const int tid = threadIdx.x;
    const int tx  = tid & 15;
    const int ty  = tid >> 4;

    u64 acc2[4][4];
#pragma unroll
    for (int i = 0; i < 4; i++)
#pragma unroll
        for (int j = 0; j < 4; j++) acc2[i][j] = 0ull;

    const int lb = tid >> 1;
    const int lk = (tid & 1) * 16;
    const int wc = tid >> 2;
    const int wk = (tid & 3) * 8;

    const float* aptr = A + lb * Tn + k0 + lk;
    const float* wptr = W + (c0 + wc) * Tn + k0 + wk;

    float4 ra[4], rw[2];

#pragma unroll
    for (int q = 0; q < 4; q++) ra[q] = ((const float4*)aptr)[q];
#pragma unroll
    for (int q = 0; q < 2; q++) rw[q] = ((const float4*)wptr)[q];

#pragma unroll
    for (int q = 0; q < 4; q++) {
        As[0][lk + q * 4 + 0][lb] = ra[q].x;
        As[0][lk + q * 4 + 1][lb] = ra[q].y;
        As[0][lk + q * 4 + 2][lb] = ra[q].z;
        As[0][lk + q * 4 + 3][lb] = ra[q].w;
    }
#pragma unroll
    for (int q = 0; q < 2; q++) {
        Ws[0][wk + q * 4 + 0][wc] = rw[q].x;
        Ws[0][wk + q * 4 + 1][wc] = rw[q].y;
        Ws[0][wk + q * 4 + 2][wc] = rw[q].z;
        Ws[0][wk + q * 4 + 3][wc] = rw[q].w;
    }
    __syncthreads();

#pragma unroll
    for (int it = 0; it < 4; it++) {
        if (it < 3) {
            const float4* ap = (const float4*)(aptr + (it + 1) * KC);
            const float4* wp = (const float4*)(wptr + (it + 1) * KC);
#pragma unroll
            for (int q = 0; q < 4; q++) ra[q] = ap[q];
#pragma unroll
            for (int q = 0; q < 2; q++) rw[q] = wp[q];
        }

        const int buf = it & 1;
#pragma unroll
        for (int kk = 0; kk < KC; kk++) {
            u64 a2[4];
            const u64* ap2 = (const u64*)&As[buf][kk][ty * 8];
#pragma unroll
            for (int i = 0; i < 4; i++) a2[i] = ap2[i];

            float wr[4];
            *(float4*)&wr[0] = *(const float4*)&Ws[buf][kk][tx * 4];
            u64 w2[4];
#pragma unroll
            for (int j = 0; j < 4; j++) w2[j] = f2pack(wr[j], wr[j]);

#pragma unroll
            for (int i = 0; i < 4; i++)
#pragma unroll
                for (int j = 0; j < 4; j++)
                    acc2[i][j] = f2fma(a2[i], w2[j], acc2[i][j]);
        }

        if (it < 3) {
            const int nb = (it + 1) & 1;
#pragma unroll
            for (int q = 0; q < 4; q++) {
                As[nb][lk + q * 4 + 0][lb] = ra[q].x;
                As[nb][lk + q * 4 + 1][lb] = ra[q].y;
                As[nb][lk + q * 4 + 2][lb] = ra[q].z;
                As[nb][lk + q * 4 + 3][lb] = ra[q].w;
            }
#pragma unroll
            for (int q = 0; q < 2; q++) {
                Ws[nb][wk + q * 4 + 0][wc] = rw[q].x;
                Ws[nb][wk + q * 4 + 1][wc] = rw[q].y;
                Ws[nb][wk + q * 4 + 2][wc] = rw[q].z;
                Ws[nb][wk + q * 4 + 3][wc] = rw[q].w;
            }
            __syncthreads();
        }
    }

#pragma unroll
    for (int i = 0; i < 4; i++) {
        int bb = ty * 8 + 2 * i;
#pragma unroll
        for (int j = 0; j < 4; j++) {
            float2 f = f2unpack(acc2[i][j]);
            atomicAdd(&g_acc[(bb)     * Cn + c0 + tx * 4 + j], f.x);
            atomicAdd(&g_acc[(bb + 1) * Cn + c0 + tx * 4 + j], f.y);
        }
    }
}

// ---------------------------------------------------------------------------
// Kernel 3: bias + relu epilogue
// ---------------------------------------------------------------------------
__global__ __launch_bounds__(256) void epilogue_kernel(
    const float* __restrict__ bfv,
    const float* __restrict__ bft,
    float* __restrict__ out)
{
    const float* g_acc = g_zero + Bn * Tn;
    int i = blockIdx.x * 256 + threadIdx.x;
    int c = i & (Cn - 1);
    float v = g_acc[i] + bfv[c] + bft[c];
    out[i] = v > 0.f ? v : 0.f;
}

// ---------------------------------------------------------------------------
extern "C" void kernel_launch(void* const* d_in, const int* in_sizes, int n_in,
                              void* d_out, int out_size)
{
    const float* vis    = (const float*)d_in[0];
    const float* txt    = (const float*)d_in[1];
    const float* w_vis  = (const float*)d_in[2];
    const float* w_text = (const float*)d_in[3];
    const float* bias   = (const float*)d_in[4];
    const float* Wfv    = (const float*)d_in[5];
    const float* bfv    = (const float*)d_in[6];
    const float* Wft    = (const float*)d_in[7];
    const float* bft    = (const float*)d_in[8];
    float* out = (float*)d_out;

    void* z_ptr = nullptr;
    cudaGetSymbolAddress(&z_ptr, g_zero);
    cudaMemsetAsync(z_ptr, 0, (Bn * Tn + Bn * Cn) * sizeof(float));

    // slab (8*Tn half2 = 32KB) + wy (Tn float2 = 8KB) + g2 (8 half2)
    const int smem_bytes = 8 * Tn * (int)sizeof(__half2)
                         + Tn * (int)sizeof(float2)
                         + 8 * (int)sizeof(__half2);
    cudaFuncSetAttribute(attn_pass_kernel,
                         cudaFuncAttributeMaxDynamicSharedMemorySize, smem_bytes);

    dim3 g1(Vn / VT, Bn);
    attn_pass_kernel<<<g1, 256, smem_bytes>>>(vis, txt, w_vis, w_text, bias);

    dim3 g2(16, 16);
    gemm_split_kernel<<<g2, 256>>>(Wfv, Wft);

    epilogue_kernel<<<(Bn * Cn) / 256, 256>>>(bfv, bft, out);
}